// round 3
// baseline (speedup 1.0000x reference)
#include <cuda_runtime.h>
#include <cstdint>

// scratch (no allocations allowed)
__device__ float g_h[134217728];   // [E*B][y][x][128co] relu(conv1), tf32-rounded
__device__ float g_xnhwc[8388608]; // [B][y][x][64ci] tf32-rounded
__device__ float g_y[16777216];    // [B][y][x][128co] combined (pre-GN)
__device__ float g_w1p[589824];    // [tap][ci][e][co]
__device__ float g_w2p[1179648];   // [e][tap][ci][co]
__device__ float g_wrp[65536];     // [e][ci][co]
__device__ float g_gates[4096];    // [B][pr][pc][E]
__device__ float g_gsum[64], g_gsq[64];

__device__ __forceinline__ float rna(float x) {
    uint32_t u; asm("cvt.rna.tf32.f32 %0,%1;" : "=r"(u) : "f"(x));
    return __uint_as_float(u);
}
__device__ __forceinline__ void mma8(float* c, const uint32_t* a, const uint32_t* b) {
    asm volatile("mma.sync.aligned.m16n8k8.row.col.f32.tf32.tf32.f32 "
        "{%0,%1,%2,%3},{%4,%5,%6,%7},{%8,%9},{%0,%1,%2,%3};"
        : "+f"(c[0]), "+f"(c[1]), "+f"(c[2]), "+f"(c[3])
        : "r"(a[0]), "r"(a[1]), "r"(a[2]), "r"(a[3]), "r"(b[0]), "r"(b[1]));
}

// K=64 of the 128pix x 128ch CTA GEMM. A pixel-major [tileRow*ARS+col][ASTR], B [k][136].
template<int ARS, int ASTR>
__device__ __forceinline__ void ksteps8(const float* As, int aBase, const float* Ws,
                                        int mbase, int nbase, int lane, float acc[2][8][4]) {
#pragma unroll
    for (int k0 = 0; k0 < 64; k0 += 8) {
        uint32_t a[2][4], bq[8][2];
        int kr = k0 + (lane & 3);
#pragma unroll
        for (int mt = 0; mt < 2; mt++) {
            int p0 = mbase + mt * 16 + (lane >> 2), p1 = p0 + 8;
            int ad0 = aBase + ((p0 >> 4) * ARS + (p0 & 15)) * ASTR;
            int ad1 = aBase + ((p1 >> 4) * ARS + (p1 & 15)) * ASTR;
            a[mt][0] = __float_as_uint(As[ad0 + kr]);
            a[mt][1] = __float_as_uint(As[ad1 + kr]);
            a[mt][2] = __float_as_uint(As[ad0 + kr + 4]);
            a[mt][3] = __float_as_uint(As[ad1 + kr + 4]);
        }
#pragma unroll
        for (int nt = 0; nt < 8; nt++) {
            int n = nbase + nt * 8 + (lane >> 2);
            bq[nt][0] = __float_as_uint(Ws[kr * 136 + n]);
            bq[nt][1] = __float_as_uint(Ws[(kr + 4) * 136 + n]);
        }
#pragma unroll
        for (int mt = 0; mt < 2; mt++)
#pragma unroll
            for (int nt = 0; nt < 8; nt++) mma8(acc[mt][nt], a[mt], bq[nt]);
    }
}

// ---------------- router ----------------
__global__ void router_kernel(const float* __restrict__ x,
                              const float* __restrict__ Rw1, const float* __restrict__ Rb1,
                              const float* __restrict__ Rw2, const float* __restrict__ Rb2) {
    __shared__ float gf[80], hb[128], lg[8];
    int pid = blockIdx.x, b = pid >> 6, pr = (pid >> 3) & 7, pc = pid & 7;
    int t = threadIdx.x;
    if (t < 64) {
        const float* xp = x + ((size_t)(b * 64 + t) * 128 + pr * 16) * 128 + pc * 16;
        float s = 0.f;
        for (int yy = 0; yy < 16; yy++)
#pragma unroll
            for (int xx = 0; xx < 16; xx++) s += xp[yy * 128 + xx];
        gf[t] = s * (1.f / 256.f);
    } else if (t < 80) {
        int i = t - 64, j = i & 3, kind = i >> 2;
        float fr = 3.14159265358979323846f * (float)(1 << j);
        float co = (kind < 2) ? ((pr + 0.5f) / 8.f) : ((pc + 0.5f) / 8.f);
        float a = co * fr;
        gf[t] = (kind & 1) ? cosf(a) : sinf(a);
    }
    __syncthreads();
    float acc = Rb1[t];
    for (int c = 0; c < 80; c++) acc += gf[c] * Rw1[c * 128 + t];
    hb[t] = fmaxf(acc, 0.f);
    __syncthreads();
    if (t < 8) {
        float l = Rb2[t];
        for (int d = 0; d < 128; d++) l += hb[d] * Rw2[d * 8 + t];
        lg[t] = l;
    }
    __syncthreads();
    if (t == 0) {
        float m = lg[0];
        for (int i = 1; i < 8; i++) m = fmaxf(m, lg[i]);
        float ex[8], ss = 0.f;
        for (int i = 0; i < 8; i++) { ex[i] = expf(lg[i] - m); ss += ex[i]; }
        for (int i = 0; i < 8; i++) g_gates[pid * 8 + i] = ex[i] / ss;
    }
}

// ---------------- x NCHW -> NHWC (tf32-rounded) ----------------
__global__ void transpose_kernel(const float* __restrict__ x) {
    __shared__ float s[64 * 129];
    int b = blockIdx.x >> 7, y = blockIdx.x & 127, t = threadIdx.x;
#pragma unroll
    for (int i = 0; i < 32; i++) {
        int idx = i * 256 + t, xx = idx & 127, c = idx >> 7;
        s[c * 129 + xx] = x[((size_t)(b * 64 + c) * 128 + y) * 128 + xx];
    }
    __syncthreads();
#pragma unroll
    for (int i = 0; i < 32; i++) {
        int idx = i * 256 + t, c = idx & 63, xx = idx >> 6;
        g_xnhwc[((b * 128 + y) * 128 + xx) * 64 + c] = rna(s[c * 129 + xx]);
    }
}

// ---------------- weight repack (tf32-rounded) ----------------
__global__ void prep_kernel(const float* __restrict__ W1, const float* __restrict__ W2,
                            const float* __restrict__ Wr) {
    int idx = blockIdx.x * 256 + threadIdx.x;
    if (idx < 589824) {
        int co = idx & 127, e = (idx >> 7) & 7, ci = (idx >> 10) & 63, tap = idx >> 16;
        g_w1p[idx] = rna(W1[((e * 128 + co) * 64 + ci) * 9 + tap]);
    } else if (idx < 589824 + 1179648) {
        int j = idx - 589824;
        int co = j & 127, ci = (j >> 7) & 127, r = j >> 14, tap = r % 9, e = r / 9;
        g_w2p[j] = rna(W2[((e * 128 + co) * 128 + ci) * 9 + tap]);
    } else if (idx < 1835008) {
        int j = idx - 1769472;
        int co = j & 127, ci = (j >> 7) & 63, e = j >> 13;
        g_wrp[j] = rna(Wr[(e * 128 + co) * 64 + ci]);
    }
}

// ---------------- conv1: h = relu(conv3x3(x,W1[e])+b1[e]) ----------------
__global__ void __launch_bounds__(256, 2) conv1_kernel(const float* __restrict__ b1) {
    extern __shared__ float sm[];
    float* xs = sm;            // 180*68 = 12240
    float* ws = sm + 12240;    // 64*136 = 8704
    float* bsm = sm + 20944;   // 128
    int t = threadIdx.x, lane = t & 31, w = t >> 5;
    int tile = blockIdx.x, e = blockIdx.y, b = blockIdx.z;
    int r0 = (tile >> 3) * 8, c0 = (tile & 7) * 16;
    for (int idx = t; idx < 2880; idx += 256) {   // 180 pix x 16 float4
        int pix = idx >> 4, c4 = (idx & 15) * 4;
        int rr = pix / 18, cc = pix % 18, gr = r0 + rr - 1, gc = c0 + cc - 1;
        float4 v = make_float4(0.f, 0.f, 0.f, 0.f);
        if (gr >= 0 && gr < 128 && gc >= 0 && gc < 128)
            v = *(const float4*)(g_xnhwc + ((size_t)(b * 128 + gr) * 128 + gc) * 64 + c4);
        *(float4*)(xs + pix * 68 + c4) = v;
    }
    if (t < 128) bsm[t] = b1[e * 128 + t];
    float acc[2][8][4] = {};
    int mbase = (w >> 1) * 32, nbase = (w & 1) * 64;
#pragma unroll 1
    for (int tap = 0; tap < 9; tap++) {
        __syncthreads();
        for (int idx = t; idx < 2048; idx += 256) {
            int ci = idx >> 5, c4 = (idx & 31) * 4;
            *(float4*)(ws + ci * 136 + c4) =
                *(const float4*)(g_w1p + ((tap * 64 + ci) * 8 + e) * 128 + c4);
        }
        __syncthreads();
        ksteps8<18, 68>(xs, ((tap / 3) * 18 + tap % 3) * 68, ws, mbase, nbase, lane, acc);
    }
    float* hb = g_h + ((size_t)(e * 8 + b) << 21);
#pragma unroll
    for (int mt = 0; mt < 2; mt++) {
        int p0 = mbase + mt * 16 + (lane >> 2);
        int py = r0 + (p0 >> 4), px = c0 + (p0 & 15);
#pragma unroll
        for (int nt = 0; nt < 8; nt++) {
            int co = nbase + nt * 8 + (lane & 3) * 2;
            size_t base = ((size_t)py * 128 + px) * 128 + co;
            float2 v0, v1;
            v0.x = rna(fmaxf(acc[mt][nt][0] + bsm[co], 0.f));
            v0.y = rna(fmaxf(acc[mt][nt][1] + bsm[co + 1], 0.f));
            v1.x = rna(fmaxf(acc[mt][nt][2] + bsm[co], 0.f));
            v1.y = rna(fmaxf(acc[mt][nt][3] + bsm[co + 1], 0.f));
            *(float2*)(hb + base) = v0;
            *(float2*)(hb + base + 1024) = v1;
        }
    }
}

// ------- conv2 + 1x1 residual + bias + relu + gated combine -> g_y -------
__global__ void __launch_bounds__(256, 1) conv2_kernel(const float* __restrict__ b2,
                                                       const float* __restrict__ br) {
    extern __shared__ float sm[];
    float* hs = sm;            // 180*132 = 23760
    float* ws = sm + 23760;    // 8704
    float* xr = sm + 32464;    // 128*68 = 8704
    float* bsm = sm + 41168;   // 1024
    float* gsm = sm + 42192;   // 8
    int t = threadIdx.x, lane = t & 31, w = t >> 5;
    int tile = blockIdx.x, b = blockIdx.y;
    int r0 = (tile >> 3) * 8, c0 = (tile & 7) * 16;
    for (int idx = t; idx < 2048; idx += 256) {   // xr: 128 pix x 16 float4
        int pix = idx >> 4, c4 = (idx & 15) * 4;
        int gr = r0 + (pix >> 4), gc = c0 + (pix & 15);
        *(float4*)(xr + pix * 68 + c4) =
            *(const float4*)(g_xnhwc + ((size_t)(b * 128 + gr) * 128 + gc) * 64 + c4);
    }
    for (int idx = t; idx < 1024; idx += 256) bsm[idx] = b2[idx] + br[idx];
    if (t < 8) gsm[t] = g_gates[(b * 64 + (tile >> 4) * 8 + (tile & 7)) * 8 + t];
    float comb[2][8][4] = {};
    int mbase = (w >> 1) * 32, nbase = (w & 1) * 64;
#pragma unroll 1
    for (int e = 0; e < 8; e++) {
        __syncthreads();
        const float* hbase = g_h + ((size_t)(e * 8 + b) << 21);
        for (int idx = t; idx < 5760; idx += 256) {  // hs: 180 pix x 32 float4
            int pix = idx >> 5, c4 = (idx & 31) * 4;
            int rr = pix / 18, cc = pix % 18, gr = r0 + rr - 1, gc = c0 + cc - 1;
            float4 v = make_float4(0.f, 0.f, 0.f, 0.f);
            if (gr >= 0 && gr < 128 && gc >= 0 && gc < 128)
                v = *(const float4*)(hbase + ((size_t)gr * 128 + gc) * 128 + c4);
            *(float4*)(hs + pix * 132 + c4) = v;
        }
        for (int idx = t; idx < 2048; idx += 256) {  // residual weights
            int ci = idx >> 5, c4 = (idx & 31) * 4;
            *(float4*)(ws + ci * 136 + c4) = *(const float4*)(g_wrp + (e * 64 + ci) * 128 + c4);
        }
        __syncthreads();
        float acc[2][8][4] = {};
        ksteps8<16, 68>(xr, 0, ws, mbase, nbase, lane, acc);
#pragma unroll 1
        for (int tc = 0; tc < 18; tc++) {            // 9 taps x 2 k-chunks
            int tap = tc >> 1, ch = tc & 1;
            __syncthreads();
            for (int idx = t; idx < 2048; idx += 256) {
                int ci = idx >> 5, c4 = (idx & 31) * 4;
                *(float4*)(ws + ci * 136 + c4) =
                    *(const float4*)(g_w2p + (((e * 9 + tap) * 128) + ch * 64 + ci) * 128 + c4);
            }
            __syncthreads();
            ksteps8<18, 132>(hs, ((tap / 3) * 18 + tap % 3) * 132 + ch * 64,
                             ws, mbase, nbase, lane, acc);
        }
        float g = gsm[e];
#pragma unroll
        for (int mt = 0; mt < 2; mt++)
#pragma unroll
            for (int nt = 0; nt < 8; nt++) {
                int co = nbase + nt * 8 + (lane & 3) * 2;
                float bb0 = bsm[e * 128 + co], bb1 = bsm[e * 128 + co + 1];
                comb[mt][nt][0] += g * fmaxf(acc[mt][nt][0] + bb0, 0.f);
                comb[mt][nt][1] += g * fmaxf(acc[mt][nt][1] + bb1, 0.f);
                comb[mt][nt][2] += g * fmaxf(acc[mt][nt][2] + bb0, 0.f);
                comb[mt][nt][3] += g * fmaxf(acc[mt][nt][3] + bb1, 0.f);
            }
    }
    float* yb = g_y + ((size_t)b << 21);
#pragma unroll
    for (int mt = 0; mt < 2; mt++) {
        int p0 = mbase + mt * 16 + (lane >> 2);
        int py = r0 + (p0 >> 4), px = c0 + (p0 & 15);
#pragma unroll
        for (int nt = 0; nt < 8; nt++) {
            int co = nbase + nt * 8 + (lane & 3) * 2;
            size_t base = ((size_t)py * 128 + px) * 128 + co;
            *(float2*)(yb + base) = make_float2(comb[mt][nt][0], comb[mt][nt][1]);
            *(float2*)(yb + base + 1024) = make_float2(comb[mt][nt][2], comb[mt][nt][3]);
        }
    }
}

// ---------------- GroupNorm stats ----------------
__global__ void gnstat_kernel() {
    __shared__ float s1[256], s2[256];
    int bg = blockIdx.x, b = bg >> 3, g = bg & 7, t = threadIdx.x;
    const float* yb = g_y + ((size_t)b << 21);
    float s = 0.f, q = 0.f;
    for (int i = t; i < 262144; i += 256) {
        float v = yb[(size_t)(i >> 4) * 128 + g * 16 + (i & 15)];
        s += v; q += v * v;
    }
    s1[t] = s; s2[t] = q;
    __syncthreads();
    for (int o = 128; o; o >>= 1) {
        if (t < o) { s1[t] += s1[t + o]; s2[t] += s2[t + o]; }
        __syncthreads();
    }
    if (t == 0) { g_gsum[bg] = s1[0]; g_gsq[bg] = s2[0]; }
}

// ---------------- normalize + NHWC -> NCHW ----------------
__global__ void finalize_kernel(float* __restrict__ out, const float* __restrict__ gamma,
                                const float* __restrict__ beta) {
    extern __shared__ float s[];   // 128*129
    int b = blockIdx.x >> 7, y = blockIdx.x & 127, t = threadIdx.x;
    const float* yb = g_y + (((size_t)b * 16384) + y * 128) * 128;
#pragma unroll 4
    for (int i = 0; i < 64; i++) {
        int idx = i * 256 + t, xx = idx >> 7, co = idx & 127;
        s[xx * 129 + co] = yb[xx * 128 + co];
    }
    __syncthreads();
#pragma unroll 4
    for (int i = 0; i < 64; i++) {
        int idx = i * 256 + t, co = idx >> 7, xx = idx & 127, g = co >> 4;
        float mu = g_gsum[b * 8 + g] * (1.f / 262144.f);
        float var = g_gsq[b * 8 + g] * (1.f / 262144.f) - mu * mu;
        float inv = rsqrtf(var + 1e-5f);
        out[(((size_t)b * 128 + co) * 128 + y) * 128 + xx] =
            (s[xx * 129 + co] - mu) * inv * gamma[co] + beta[co];
    }
}

extern "C" void kernel_launch(void* const* d_in, const int* in_sizes, int n_in,
                              void* d_out, int out_size) {
    const float* x   = (const float*)d_in[0];
    const float* W1  = (const float*)d_in[1];
    const float* b1  = (const float*)d_in[2];
    const float* W2  = (const float*)d_in[3];
    const float* b2  = (const float*)d_in[4];
    const float* Wr  = (const float*)d_in[5];
    const float* br  = (const float*)d_in[6];
    const float* Rw1 = (const float*)d_in[7];
    const float* Rb1 = (const float*)d_in[8];
    const float* Rw2 = (const float*)d_in[9];
    const float* Rb2 = (const float*)d_in[10];
    const float* gamma = (const float*)d_in[11];
    const float* beta  = (const float*)d_in[12];
    float* out = (float*)d_out;

    cudaFuncSetAttribute(conv1_kernel, cudaFuncAttributeMaxDynamicSharedMemorySize, 84288);
    cudaFuncSetAttribute(conv2_kernel, cudaFuncAttributeMaxDynamicSharedMemorySize, 168800);
    cudaFuncSetAttribute(finalize_kernel, cudaFuncAttributeMaxDynamicSharedMemorySize, 66048);

    router_kernel<<<512, 128>>>(x, Rw1, Rb1, Rw2, Rb2);
    transpose_kernel<<<1024, 256>>>(x);
    prep_kernel<<<7168, 256>>>(W1, W2, Wr);
    conv1_kernel<<<dim3(128, 8, 8), 256, 84288>>>(b1);
    conv2_kernel<<<dim3(128, 8), 256, 168800>>>(b2, br);
    gnstat_kernel<<<64, 256>>>();
    finalize_kernel<<<1024, 256, 66048>>>(out, gamma, beta);
}

// round 8
// speedup vs baseline: 1.3481x; 1.3481x over previous
#include <cuda_runtime.h>
#include <cstdint>

__device__ float g_h[134217728];   // [E*B][y][x][128co]
__device__ float g_xnhwc[8388608]; // [B][y][x][64ci]
__device__ float g_y[16777216];    // [B][y][x][128co]
__device__ float g_w1p[589824];    // [tap][ci][e][co]
__device__ float g_w2p[1179648];   // [e][tap][ci][co]
__device__ float g_wrp[65536];     // [e][ci][co]
__device__ float g_gates[4096];
__device__ float g_p1[512], g_p2[512];

#define CPC asm volatile("cp.async.commit_group;\n" ::: "memory")
#define CPW0 asm volatile("cp.async.wait_group 0;\n" ::: "memory")
#define CPW1 asm volatile("cp.async.wait_group 1;\n" ::: "memory")

__device__ __forceinline__ uint32_t s2u(const void* p) {
    return (uint32_t)__cvta_generic_to_shared(p);
}
__device__ __forceinline__ void cpa(uint32_t d, const void* s, bool v) {
    int sz = v ? 16 : 0;
    asm volatile("cp.async.cg.shared.global [%0],[%1],16,%2;\n" :: "r"(d), "l"(s), "r"(sz));
}
__device__ __forceinline__ float rna(float x) {
    uint32_t u; asm("cvt.rna.tf32.f32 %0,%1;" : "=r"(u) : "f"(x));
    return __uint_as_float(u);
}
__device__ __forceinline__ void mma8(float* c, const uint32_t* a, const uint32_t* b) {
    asm volatile("mma.sync.aligned.m16n8k8.row.col.f32.tf32.tf32.f32 "
        "{%0,%1,%2,%3},{%4,%5,%6,%7},{%8,%9},{%0,%1,%2,%3};"
        : "+f"(c[0]), "+f"(c[1]), "+f"(c[2]), "+f"(c[3])
        : "r"(a[0]), "r"(a[1]), "r"(a[2]), "r"(a[3]), "r"(b[0]), "r"(b[1]));
}

// K=64 of a (pix)x(128ch) GEMM. A pixel-major [(p>>4)*ARS + (p&15)][ASTR], B [k][136].
template<int ARS, int ASTR>
__device__ __forceinline__ void ksteps8(const float* As, int aBase, const float* Ws,
                                        int mbase, int nbase, int lane, float acc[2][8][4]) {
#pragma unroll
    for (int k0 = 0; k0 < 64; k0 += 8) {
        uint32_t a[2][4], bq[8][2];
        int kr = k0 + (lane & 3);
#pragma unroll
        for (int mt = 0; mt < 2; mt++) {
            int p0 = mbase + mt * 16 + (lane >> 2), p1 = p0 + 8;
            int ad0 = aBase + ((p0 >> 4) * ARS + (p0 & 15)) * ASTR;
            int ad1 = aBase + ((p1 >> 4) * ARS + (p1 & 15)) * ASTR;
            a[mt][0] = __float_as_uint(As[ad0 + kr]);
            a[mt][1] = __float_as_uint(As[ad1 + kr]);
            a[mt][2] = __float_as_uint(As[ad0 + kr + 4]);
            a[mt][3] = __float_as_uint(As[ad1 + kr + 4]);
        }
#pragma unroll
        for (int nt = 0; nt < 8; nt++) {
            int n = nbase + nt * 8 + (lane >> 2);
            bq[nt][0] = __float_as_uint(Ws[kr * 136 + n]);
            bq[nt][1] = __float_as_uint(Ws[(kr + 4) * 136 + n]);
        }
#pragma unroll
        for (int mt = 0; mt < 2; mt++)
#pragma unroll
            for (int nt = 0; nt < 8; nt++) mma8(acc[mt][nt], a[mt], bq[nt]);
    }
}

// ---------------- router ----------------
__global__ void router_kernel(const float* __restrict__ x,
                              const float* __restrict__ Rw1, const float* __restrict__ Rb1,
                              const float* __restrict__ Rw2, const float* __restrict__ Rb2) {
    __shared__ float gf[80], hb[128], lg[8];
    int pid = blockIdx.x, b = pid >> 6, pr = (pid >> 3) & 7, pc = pid & 7;
    int t = threadIdx.x;
    if (t < 64) {
        const float* xp = x + ((size_t)(b * 64 + t) * 128 + pr * 16) * 128 + pc * 16;
        float s = 0.f;
        for (int yy = 0; yy < 16; yy++)
#pragma unroll
            for (int xx = 0; xx < 16; xx++) s += xp[yy * 128 + xx];
        gf[t] = s * (1.f / 256.f);
    } else if (t < 80) {
        int i = t - 64, j = i & 3, kind = i >> 2;
        float fr = 3.14159265358979323846f * (float)(1 << j);
        float co = (kind < 2) ? ((pr + 0.5f) / 8.f) : ((pc + 0.5f) / 8.f);
        float a = co * fr;
        gf[t] = (kind & 1) ? cosf(a) : sinf(a);
    }
    __syncthreads();
    float acc = Rb1[t];
    for (int c = 0; c < 80; c++) acc += gf[c] * Rw1[c * 128 + t];
    hb[t] = fmaxf(acc, 0.f);
    __syncthreads();
    if (t < 8) {
        float l = Rb2[t];
        for (int d = 0; d < 128; d++) l += hb[d] * Rw2[d * 8 + t];
        lg[t] = l;
    }
    __syncthreads();
    if (t == 0) {
        float m = lg[0];
        for (int i = 1; i < 8; i++) m = fmaxf(m, lg[i]);
        float ex[8], ss = 0.f;
        for (int i = 0; i < 8; i++) { ex[i] = expf(lg[i] - m); ss += ex[i]; }
        for (int i = 0; i < 8; i++) g_gates[pid * 8 + i] = ex[i] / ss;
    }
}

// ---------------- x NCHW -> NHWC (tf32-rounded) ----------------
__global__ void transpose_kernel(const float* __restrict__ x) {
    __shared__ float s[64 * 129];
    int b = blockIdx.x >> 7, y = blockIdx.x & 127, t = threadIdx.x;
#pragma unroll
    for (int i = 0; i < 32; i++) {
        int idx = i * 256 + t, xx = idx & 127, c = idx >> 7;
        s[c * 129 + xx] = x[((size_t)(b * 64 + c) * 128 + y) * 128 + xx];
    }
    __syncthreads();
#pragma unroll
    for (int i = 0; i < 32; i++) {
        int idx = i * 256 + t, c = idx & 63, xx = idx >> 6;
        g_xnhwc[((b * 128 + y) * 128 + xx) * 64 + c] = rna(s[c * 129 + xx]);
    }
}

// ---------------- weight repack (tf32-rounded) ----------------
__global__ void prep_kernel(const float* __restrict__ W1, const float* __restrict__ W2,
                            const float* __restrict__ Wr) {
    int idx = blockIdx.x * 256 + threadIdx.x;
    if (idx < 589824) {
        int co = idx & 127, e = (idx >> 7) & 7, ci = (idx >> 10) & 63, tap = idx >> 16;
        g_w1p[idx] = rna(W1[((e * 128 + co) * 64 + ci) * 9 + tap]);
    } else if (idx < 589824 + 1179648) {
        int j = idx - 589824;
        int co = j & 127, ci = (j >> 7) & 127, r = j >> 14, tap = r % 9, e = r / 9;
        g_w2p[j] = rna(W2[((e * 128 + co) * 128 + ci) * 9 + tap]);
    } else if (idx < 1835008) {
        int j = idx - 1769472;
        int co = j & 127, ci = (j >> 7) & 63, e = j >> 13;
        g_wrp[j] = rna(Wr[(e * 128 + co) * 64 + ci]);
    }
}

// ---- conv1: 512 thr, 256-pix tile, double-buffered weights ----
__global__ void __launch_bounds__(512, 1) conv1_kernel(const float* __restrict__ b1) {
    extern __shared__ float sm[];
    float* xs = sm;             // 324*68 = 22032
    float* w0 = sm + 22032;     // 8704
    float* w1 = sm + 30736;     // 8704
    float* bsm = sm + 39440;    // 128
    int t = threadIdx.x, lane = t & 31, w = t >> 5;
    int tile = blockIdx.x, e = blockIdx.y, b = blockIdx.z;
    int r0 = (tile >> 3) * 16, c0 = (tile & 7) * 16;
    for (int idx = t; idx < 5184; idx += 512) {     // 324 pix x 16 float4
        int pix = idx >> 4, c4 = (idx & 15) * 4;
        int rr = pix / 18, cc = pix % 18, gr = r0 + rr - 1, gc = c0 + cc - 1;
        bool v = gr >= 0 && gr < 128 && gc >= 0 && gc < 128;
        cpa(s2u(xs + pix * 68 + c4),
            g_xnhwc + ((size_t)(b * 128 + (v ? gr : 0)) * 128 + (v ? gc : 0)) * 64 + c4, v);
    }
    for (int idx = t; idx < 2048; idx += 512) {
        int ci = idx >> 5, c4 = (idx & 31) * 4;
        cpa(s2u(w0 + ci * 136 + c4), g_w1p + ((size_t)ci * 8 + e) * 128 + c4, true);
    }
    CPC;
    if (t < 128) bsm[t] = b1[e * 128 + t];
    CPW0; __syncthreads();
    float acc[2][8][4] = {};
    int mbase = (w >> 1) * 32, nbase = (w & 1) * 64;
#pragma unroll 1
    for (int tap = 0; tap < 9; tap++) {
        float* wc = (tap & 1) ? w1 : w0;
        if (tap < 8) {
            float* wn = (tap & 1) ? w0 : w1;
            for (int idx = t; idx < 2048; idx += 512) {
                int ci = idx >> 5, c4 = (idx & 31) * 4;
                cpa(s2u(wn + ci * 136 + c4),
                    g_w1p + (((size_t)(tap + 1) * 64 + ci) * 8 + e) * 128 + c4, true);
            }
            CPC;
        }
        ksteps8<18, 68>(xs, ((tap / 3) * 18 + tap % 3) * 68, wc, mbase, nbase, lane, acc);
        __syncthreads();
        if (tap < 8) { CPW0; __syncthreads(); }
    }
    float* hb = g_h + ((size_t)(e * 8 + b) << 21);
#pragma unroll
    for (int mt = 0; mt < 2; mt++) {
        int p0 = mbase + mt * 16 + (lane >> 2);
        int py = r0 + (p0 >> 4), px = c0 + (p0 & 15);
#pragma unroll
        for (int nt = 0; nt < 8; nt++) {
            int co = nbase + nt * 8 + (lane & 3) * 2;
            size_t base = ((size_t)py * 128 + px) * 128 + co;
            float2 v0, v1;
            v0.x = rna(fmaxf(acc[mt][nt][0] + bsm[co], 0.f));
            v0.y = rna(fmaxf(acc[mt][nt][1] + bsm[co + 1], 0.f));
            v1.x = rna(fmaxf(acc[mt][nt][2] + bsm[co], 0.f));
            v1.y = rna(fmaxf(acc[mt][nt][3] + bsm[co + 1], 0.f));
            *(float2*)(hb + base) = v0;
            *(float2*)(hb + base + 1024) = v1;
        }
    }
}

// ---- conv2: k-halved h tile, double-buffered weights, pipelined ----
__global__ void __launch_bounds__(256, 1) conv2_kernel(const float* __restrict__ b2,
                                                       const float* __restrict__ br) {
    extern __shared__ float sm[];
    float* buf = sm;            // 180*68 = 12240
    float* w0 = sm + 12240;     // 8704
    float* w1 = sm + 20944;     // 8704
    float* bsm = sm + 29648;    // 1024
    float* gsm = sm + 30672;    // 8
    int t = threadIdx.x, lane = t & 31, w = t >> 5;
    int tile = blockIdx.x, b = blockIdx.y;
    int r0 = (tile >> 3) * 8, c0 = (tile & 7) * 16;
    for (int idx = t; idx < 1024; idx += 256) bsm[idx] = b2[idx] + br[idx];
    if (t < 8) gsm[t] = g_gates[(b * 64 + (tile >> 4) * 8 + (tile & 7)) * 8 + t];
    float comb[2][8][4] = {};
    int mbase = (w >> 1) * 32, nbase = (w & 1) * 64;
#pragma unroll 1
    for (int e = 0; e < 8; e++) {
        const float* hbase = g_h + ((size_t)(e * 8 + b) << 21);
        __syncthreads();
        for (int idx = t; idx < 2048; idx += 256) {   // xr: 128 pix x 16 float4
            int pix = idx >> 4, c4 = (idx & 15) * 4;
            int gr = r0 + (pix >> 4), gc = c0 + (pix & 15);
            cpa(s2u(buf + pix * 68 + c4),
                g_xnhwc + ((size_t)(b * 128 + gr) * 128 + gc) * 64 + c4, true);
        }
        for (int idx = t; idx < 2048; idx += 256) {
            int ci = idx >> 5, c4 = (idx & 31) * 4;
            cpa(s2u(w0 + ci * 136 + c4), g_wrp + (e * 64 + ci) * 128 + c4, true);
        }
        CPC;
        for (int idx = t; idx < 2048; idx += 256) {  // ws(stage1) -> w1
            int ci = idx >> 5, c4 = (idx & 31) * 4;
            cpa(s2u(w1 + ci * 136 + c4),
                g_w2p + ((size_t)(e * 9) * 128 + ci) * 128 + c4, true);
        }
        CPC;
        CPW1; __syncthreads();
        float acc[2][8][4] = {};
#pragma unroll 1
        for (int s = 0; s < 19; s++) {
            float* wc = (s & 1) ? w1 : w0;
            if (s == 0) {
                ksteps8<16, 68>(buf, 0, wc, mbase, nbase, lane, acc);
            } else {
                int tap = (s - 1) % 9;
                ksteps8<18, 68>(buf, ((tap / 3) * 18 + tap % 3) * 68, wc, mbase, nbase, lane, acc);
            }
            __syncthreads();                           // X: stage-s operands free
            if (s == 18) break;
            if (s == 0 || s == 9) {                    // h-halo half (kh): 180 pix x 16 float4
                int kh = (s == 0) ? 0 : 64;
                for (int idx = t; idx < 2880; idx += 256) {
                    int pix = idx >> 4, c4 = (idx & 15) * 4;
                    int rr = pix / 18, cc = pix % 18, gr = r0 + rr - 1, gc = c0 + cc - 1;
                    bool v = gr >= 0 && gr < 128 && gc >= 0 && gc < 128;
                    cpa(s2u(buf + pix * 68 + c4),
                        hbase + ((size_t)((v ? gr : 0) * 128 + (v ? gc : 0)) * 128) + kh + c4, v);
                }
                CPC;
            }
            bool more = (s + 2 <= 18);
            if (more) {                                // ws(stage s+2) -> buffer of stage s
                int s2 = s + 1, tap2 = s2 % 9, kh2 = (s2 / 9) * 64;
                float* wn = (s & 1) ? w1 : w0;
                for (int idx = t; idx < 2048; idx += 256) {
                    int ci = idx >> 5, c4 = (idx & 31) * 4;
                    cpa(s2u(wn + ci * 136 + c4),
                        g_w2p + ((size_t)(e * 9 + tap2) * 128 + kh2 + ci) * 128 + c4, true);
                }
                CPC;
            }
            if (more) { CPW1; } else { CPW0; }
            __syncthreads();                           // Y: stage s+1 operands visible
        }
        float g = gsm[e];
#pragma unroll
        for (int mt = 0; mt < 2; mt++)
#pragma unroll
            for (int nt = 0; nt < 8; nt++) {
                int co = nbase + nt * 8 + (lane & 3) * 2;
                float bb0 = bsm[e * 128 + co], bb1 = bsm[e * 128 + co + 1];
                comb[mt][nt][0] += g * fmaxf(acc[mt][nt][0] + bb0, 0.f);
                comb[mt][nt][1] += g * fmaxf(acc[mt][nt][1] + bb1, 0.f);
                comb[mt][nt][2] += g * fmaxf(acc[mt][nt][2] + bb0, 0.f);
                comb[mt][nt][3] += g * fmaxf(acc[mt][nt][3] + bb1, 0.f);
            }
    }
    float* yb = g_y + ((size_t)b << 21);
#pragma unroll
    for (int mt = 0; mt < 2; mt++) {
        int p0 = mbase + mt * 16 + (lane >> 2);
        int py = r0 + (p0 >> 4), px = c0 + (p0 & 15);
#pragma unroll
        for (int nt = 0; nt < 8; nt++) {
            int co = nbase + nt * 8 + (lane & 3) * 2;
            size_t base = ((size_t)py * 128 + px) * 128 + co;
            *(float2*)(yb + base) = make_float2(comb[mt][nt][0], comb[mt][nt][1]);
            *(float2*)(yb + base + 1024) = make_float2(comb[mt][nt][2], comb[mt][nt][3]);
        }
    }
}

// ---------------- GroupNorm partial stats (deterministic) ----------------
__global__ void gnstat_kernel() {
    __shared__ float s1[256], s2[256];
    int blk = blockIdx.x, bg = blk >> 3, part = blk & 7, b = bg >> 3, g = bg & 7;
    int t = threadIdx.x;
    const float* yb = g_y + ((size_t)b << 21);
    float s = 0.f, q = 0.f;
    for (int i = part * 32768 + t; i < part * 32768 + 32768; i += 256) {
        float v = yb[(size_t)(i >> 4) * 128 + g * 16 + (i & 15)];
        s += v; q += v * v;
    }
    s1[t] = s; s2[t] = q;
    __syncthreads();
    for (int o = 128; o; o >>= 1) {
        if (t < o) { s1[t] += s1[t + o]; s2[t] += s2[t + o]; }
        __syncthreads();
    }
    if (t == 0) { g_p1[blk] = s1[0]; g_p2[blk] = s2[0]; }
}

// ---------------- normalize + NHWC -> NCHW ----------------
__global__ void finalize_kernel(float* __restrict__ out, const float* __restrict__ gamma,
                                const float* __restrict__ beta) {
    extern __shared__ float s[];   // 128*129
    __shared__ float smu[8], sinv[8];
    int b = blockIdx.x >> 7, y = blockIdx.x & 127, t = threadIdx.x;
    if (t < 8) {
        float ss = 0.f, qq = 0.f;
        for (int p = 0; p < 8; p++) { ss += g_p1[(b * 8 + t) * 8 + p]; qq += g_p2[(b * 8 + t) * 8 + p]; }
        float mu = ss * (1.f / 262144.f);
        smu[t] = mu;
        sinv[t] = rsqrtf(qq * (1.f / 262144.f) - mu * mu + 1e-5f);
    }
    const float* yb = g_y + (((size_t)b * 16384) + y * 128) * 128;
#pragma unroll 4
    for (int i = 0; i < 64; i++) {
        int idx = i * 256 + t, xx = idx >> 7, co = idx & 127;
        s[xx * 129 + co] = yb[xx * 128 + co];
    }
    __syncthreads();
#pragma unroll 4
    for (int i = 0; i < 64; i++) {
        int idx = i * 256 + t, co = idx >> 7, xx = idx & 127, g = co >> 4;
        out[(((size_t)b * 128 + co) * 128 + y) * 128 + xx] =
            (s[xx * 129 + co] - smu[g]) * sinv[g] * gamma[co] + beta[co];
    }
}

extern "C" void kernel_launch(void* const* d_in, const int* in_sizes, int n_in,
                              void* d_out, int out_size) {
    const float* x   = (const float*)d_in[0];
    const float* W1  = (const float*)d_in[1];
    const float* b1  = (const float*)d_in[2];
    const float* W2  = (const float*)d_in[3];
    const float* b2  = (const float*)d_in[4];
    const float* Wr  = (const float*)d_in[5];
    const float* br  = (const float*)d_in[6];
    const float* Rw1 = (const float*)d_in[7];
    const float* Rb1 = (const float*)d_in[8];
    const float* Rw2 = (const float*)d_in[9];
    const float* Rb2 = (const float*)d_in[10];
    const float* gamma = (const float*)d_in[11];
    const float* beta  = (const float*)d_in[12];
    float* out = (float*)d_out;

    cudaFuncSetAttribute(conv1_kernel, cudaFuncAttributeMaxDynamicSharedMemorySize, 158272);
    cudaFuncSetAttribute(conv2_kernel, cudaFuncAttributeMaxDynamicSharedMemorySize, 122720);
    cudaFuncSetAttribute(finalize_kernel, cudaFuncAttributeMaxDynamicSharedMemorySize, 66048);

    router_kernel<<<512, 128>>>(x, Rw1, Rb1, Rw2, Rb2);
    transpose_kernel<<<1024, 256>>>(x);
    prep_kernel<<<7168, 256>>>(W1, W2, Wr);
    conv1_kernel<<<dim3(64, 8, 8), 512, 158272>>>(b1);
    conv2_kernel<<<dim3(128, 8), 256, 122720>>>(b2, br);
    gnstat_kernel<<<512, 256>>>();
    finalize_kernel<<<1024, 256, 66048>>>(out, gamma, beta);
}

// round 9
// speedup vs baseline: 1.3801x; 1.0237x over previous
#include <cuda_runtime.h>
#include <cstdint>

__device__ float g_h[134217728];   // [E*B][y][x][128co]
__device__ float g_xnhwc[8388608]; // [B][y][x][64ci]
__device__ float g_y[16777216];    // [B][y][x][128co]
__device__ float g_w1p[589824];    // [tap][ci][e][co]
__device__ float g_w2p[1179648];   // [e][tap][ci][co]
__device__ float g_wrp[65536];     // [e][ci][co]
__device__ float g_gates[4096];
__device__ float g_p1[512], g_p2[512];

#define CPC asm volatile("cp.async.commit_group;\n" ::: "memory")
#define CPW0 asm volatile("cp.async.wait_group 0;\n" ::: "memory")
#define CPW1 asm volatile("cp.async.wait_group 1;\n" ::: "memory")

__device__ __forceinline__ uint32_t s2u(const void* p) {
    return (uint32_t)__cvta_generic_to_shared(p);
}
__device__ __forceinline__ void cpa(uint32_t d, const void* s, bool v) {
    int sz = v ? 16 : 0;
    asm volatile("cp.async.cg.shared.global [%0],[%1],16,%2;\n" :: "r"(d), "l"(s), "r"(sz));
}
__device__ __forceinline__ float rna(float x) {
    uint32_t u; asm("cvt.rna.tf32.f32 %0,%1;" : "=r"(u) : "f"(x));
    return __uint_as_float(u);
}
__device__ __forceinline__ void mma8(float* c, const uint32_t* a, const uint32_t* b) {
    asm volatile("mma.sync.aligned.m16n8k8.row.col.f32.tf32.tf32.f32 "
        "{%0,%1,%2,%3},{%4,%5,%6,%7},{%8,%9},{%0,%1,%2,%3};"
        : "+f"(c[0]), "+f"(c[1]), "+f"(c[2]), "+f"(c[3])
        : "r"(a[0]), "r"(a[1]), "r"(a[2]), "r"(a[3]), "r"(b[0]), "r"(b[1]));
}

// K=64 of a (pix)x(128ch) GEMM, MT m-tiles of 16 pixels per warp.
// A pixel-major [(p>>4)*ARS + (p&15)][ASTR], B [k][136].
template<int ARS, int ASTR, int MT>
__device__ __forceinline__ void ksteps8(const float* As, int aBase, const float* Ws,
                                        int mbase, int nbase, int lane, float acc[MT][8][4]) {
#pragma unroll
    for (int k0 = 0; k0 < 64; k0 += 8) {
        uint32_t a[MT][4], bq[8][2];
        int kr = k0 + (lane & 3);
#pragma unroll
        for (int mt = 0; mt < MT; mt++) {
            int p0 = mbase + mt * 16 + (lane >> 2), p1 = p0 + 8;
            int ad0 = aBase + ((p0 >> 4) * ARS + (p0 & 15)) * ASTR;
            int ad1 = aBase + ((p1 >> 4) * ARS + (p1 & 15)) * ASTR;
            a[mt][0] = __float_as_uint(As[ad0 + kr]);
            a[mt][1] = __float_as_uint(As[ad1 + kr]);
            a[mt][2] = __float_as_uint(As[ad0 + kr + 4]);
            a[mt][3] = __float_as_uint(As[ad1 + kr + 4]);
        }
#pragma unroll
        for (int nt = 0; nt < 8; nt++) {
            int n = nbase + nt * 8 + (lane >> 2);
            bq[nt][0] = __float_as_uint(Ws[kr * 136 + n]);
            bq[nt][1] = __float_as_uint(Ws[(kr + 4) * 136 + n]);
        }
#pragma unroll
        for (int mt = 0; mt < MT; mt++)
#pragma unroll
            for (int nt = 0; nt < 8; nt++) mma8(acc[mt][nt], a[mt], bq[nt]);
    }
}

// ---------------- router ----------------
__global__ void router_kernel(const float* __restrict__ x,
                              const float* __restrict__ Rw1, const float* __restrict__ Rb1,
                              const float* __restrict__ Rw2, const float* __restrict__ Rb2) {
    __shared__ float gf[80], hb[128], lg[8];
    int pid = blockIdx.x, b = pid >> 6, pr = (pid >> 3) & 7, pc = pid & 7;
    int t = threadIdx.x;
    if (t < 64) {
        const float* xp = x + ((size_t)(b * 64 + t) * 128 + pr * 16) * 128 + pc * 16;
        float s = 0.f;
        for (int yy = 0; yy < 16; yy++)
#pragma unroll
            for (int xx = 0; xx < 16; xx++) s += xp[yy * 128 + xx];
        gf[t] = s * (1.f / 256.f);
    } else if (t < 80) {
        int i = t - 64, j = i & 3, kind = i >> 2;
        float fr = 3.14159265358979323846f * (float)(1 << j);
        float co = (kind < 2) ? ((pr + 0.5f) / 8.f) : ((pc + 0.5f) / 8.f);
        float a = co * fr;
        gf[t] = (kind & 1) ? cosf(a) : sinf(a);
    }
    __syncthreads();
    float acc = Rb1[t];
    for (int c = 0; c < 80; c++) acc += gf[c] * Rw1[c * 128 + t];
    hb[t] = fmaxf(acc, 0.f);
    __syncthreads();
    if (t < 8) {
        float l = Rb2[t];
        for (int d = 0; d < 128; d++) l += hb[d] * Rw2[d * 8 + t];
        lg[t] = l;
    }
    __syncthreads();
    if (t == 0) {
        float m = lg[0];
        for (int i = 1; i < 8; i++) m = fmaxf(m, lg[i]);
        float ex[8], ss = 0.f;
        for (int i = 0; i < 8; i++) { ex[i] = expf(lg[i] - m); ss += ex[i]; }
        for (int i = 0; i < 8; i++) g_gates[pid * 8 + i] = ex[i] / ss;
    }
}

// ---------------- x NCHW -> NHWC (tf32-rounded) ----------------
__global__ void transpose_kernel(const float* __restrict__ x) {
    __shared__ float s[64 * 129];
    int b = blockIdx.x >> 7, y = blockIdx.x & 127, t = threadIdx.x;
#pragma unroll
    for (int i = 0; i < 32; i++) {
        int idx = i * 256 + t, xx = idx & 127, c = idx >> 7;
        s[c * 129 + xx] = x[((size_t)(b * 64 + c) * 128 + y) * 128 + xx];
    }
    __syncthreads();
#pragma unroll
    for (int i = 0; i < 32; i++) {
        int idx = i * 256 + t, c = idx & 63, xx = idx >> 6;
        g_xnhwc[((b * 128 + y) * 128 + xx) * 64 + c] = rna(s[c * 129 + xx]);
    }
}

// ---------------- weight repack (tf32-rounded) ----------------
__global__ void prep_kernel(const float* __restrict__ W1, const float* __restrict__ W2,
                            const float* __restrict__ Wr) {
    int idx = blockIdx.x * 256 + threadIdx.x;
    if (idx < 589824) {
        int co = idx & 127, e = (idx >> 7) & 7, ci = (idx >> 10) & 63, tap = idx >> 16;
        g_w1p[idx] = rna(W1[((e * 128 + co) * 64 + ci) * 9 + tap]);
    } else if (idx < 589824 + 1179648) {
        int j = idx - 589824;
        int co = j & 127, ci = (j >> 7) & 127, r = j >> 14, tap = r % 9, e = r / 9;
        g_w2p[j] = rna(W2[((e * 128 + co) * 128 + ci) * 9 + tap]);
    } else if (idx < 1835008) {
        int j = idx - 1769472;
        int co = j & 127, ci = (j >> 7) & 63, e = j >> 13;
        g_wrp[j] = rna(Wr[(e * 128 + co) * 64 + ci]);
    }
}

// ---- conv1: 256 thr, warp tile 64x64, 256-pix CTA tile, db weights ----
__global__ void __launch_bounds__(256, 1) conv1_kernel(const float* __restrict__ b1) {
    extern __shared__ float sm[];
    float* xs = sm;             // 324*68 = 22032
    float* w0 = sm + 22032;     // 8704
    float* w1 = sm + 30736;     // 8704
    float* bsm = sm + 39440;    // 128
    int t = threadIdx.x, lane = t & 31, w = t >> 5;
    int tile = blockIdx.x, e = blockIdx.y, b = blockIdx.z;
    int r0 = (tile >> 3) * 16, c0 = (tile & 7) * 16;
    for (int idx = t; idx < 5184; idx += 256) {     // 324 pix x 16 float4
        int pix = idx >> 4, c4 = (idx & 15) * 4;
        int rr = pix / 18, cc = pix % 18, gr = r0 + rr - 1, gc = c0 + cc - 1;
        bool v = gr >= 0 && gr < 128 && gc >= 0 && gc < 128;
        cpa(s2u(xs + pix * 68 + c4),
            g_xnhwc + ((size_t)(b * 128 + (v ? gr : 0)) * 128 + (v ? gc : 0)) * 64 + c4, v);
    }
    for (int idx = t; idx < 2048; idx += 256) {
        int ci = idx >> 5, c4 = (idx & 31) * 4;
        cpa(s2u(w0 + ci * 136 + c4), g_w1p + ((size_t)ci * 8 + e) * 128 + c4, true);
    }
    CPC;
    if (t < 128) bsm[t] = b1[e * 128 + t];
    CPW0; __syncthreads();
    float acc[4][8][4] = {};
    int mbase = (w >> 1) * 64, nbase = (w & 1) * 64;
#pragma unroll 1
    for (int tap = 0; tap < 9; tap++) {
        float* wc = (tap & 1) ? w1 : w0;
        if (tap < 8) {
            float* wn = (tap & 1) ? w0 : w1;
            for (int idx = t; idx < 2048; idx += 256) {
                int ci = idx >> 5, c4 = (idx & 31) * 4;
                cpa(s2u(wn + ci * 136 + c4),
                    g_w1p + (((size_t)(tap + 1) * 64 + ci) * 8 + e) * 128 + c4, true);
            }
            CPC;
        }
        ksteps8<18, 68, 4>(xs, ((tap / 3) * 18 + tap % 3) * 68, wc, mbase, nbase, lane, acc);
        __syncthreads();
        if (tap < 8) { CPW0; __syncthreads(); }
    }
    float* hb = g_h + ((size_t)(e * 8 + b) << 21);
#pragma unroll
    for (int mt = 0; mt < 4; mt++) {
        int p0 = mbase + mt * 16 + (lane >> 2);
        int py = r0 + (p0 >> 4), px = c0 + (p0 & 15);
#pragma unroll
        for (int nt = 0; nt < 8; nt++) {
            int co = nbase + nt * 8 + (lane & 3) * 2;
            size_t base = ((size_t)py * 128 + px) * 128 + co;
            float2 v0, v1;
            v0.x = rna(fmaxf(acc[mt][nt][0] + bsm[co], 0.f));
            v0.y = rna(fmaxf(acc[mt][nt][1] + bsm[co + 1], 0.f));
            v1.x = rna(fmaxf(acc[mt][nt][2] + bsm[co], 0.f));
            v1.y = rna(fmaxf(acc[mt][nt][3] + bsm[co + 1], 0.f));
            *(float2*)(hb + base) = v0;
            *(float2*)(hb + base + 1024) = v1;
        }
    }
}

// ---- conv2: 2-taps-per-stage double-buffered weights, pipelined ----
// Stages per expert: 0=residual(64k); 1..5 = taps{01,23,45,67,8} kh=0;
// 6..10 = same taps kh=64. Stage s uses wa if s even else wb.
__global__ void __launch_bounds__(256, 1) conv2_kernel(const float* __restrict__ b2,
                                                       const float* __restrict__ br) {
    extern __shared__ float sm[];
    float* buf = sm;            // 180*68 = 12240
    float* wa = sm + 12240;     // 2*8704 = 17408
    float* wb = sm + 29648;     // 17408
    float* bsm = sm + 47056;    // 1024
    float* gsm = sm + 48080;    // 8
    int t = threadIdx.x, lane = t & 31, w = t >> 5;
    int tile = blockIdx.x, b = blockIdx.y;
    int r0 = (tile >> 3) * 8, c0 = (tile & 7) * 16;
    for (int idx = t; idx < 1024; idx += 256) bsm[idx] = b2[idx] + br[idx];
    if (t < 8) gsm[t] = g_gates[(b * 64 + (tile >> 4) * 8 + (tile & 7)) * 8 + t];
    float comb[2][8][4] = {};
    int mbase = (w >> 1) * 32, nbase = (w & 1) * 64;
#pragma unroll 1
    for (int e = 0; e < 8; e++) {
        const float* hbase = g_h + ((size_t)(e * 8 + b) << 21);
        __syncthreads();
        for (int idx = t; idx < 2048; idx += 256) {   // xr: 128 pix (no halo)
            int pix = idx >> 4, c4 = (idx & 15) * 4;
            int gr = r0 + (pix >> 4), gc = c0 + (pix & 15);
            cpa(s2u(buf + pix * 68 + c4),
                g_xnhwc + ((size_t)(b * 128 + gr) * 128 + gc) * 64 + c4, true);
        }
        for (int idx = t; idx < 2048; idx += 256) {   // residual weights -> wa
            int ci = idx >> 5, c4 = (idx & 31) * 4;
            cpa(s2u(wa + ci * 136 + c4), g_wrp + (e * 64 + ci) * 128 + c4, true);
        }
        CPC;
        for (int idx = t; idx < 4096; idx += 256) {   // stage1 (taps 0,1 kh0) -> wb
            int ti = idx >> 11, rem = idx & 2047;
            int ci = rem >> 5, c4 = (rem & 31) * 4;
            cpa(s2u(wb + ti * 8704 + ci * 136 + c4),
                g_w2p + ((size_t)(e * 9 + ti) * 128 + ci) * 128 + c4, true);
        }
        CPC;
        CPW1; __syncthreads();
        float acc[2][8][4] = {};
#pragma unroll 1
        for (int s = 0; s < 11; s++) {
            float* wc = (s & 1) ? wb : wa;
            if (s == 0) {
                ksteps8<16, 68, 2>(buf, 0, wc, mbase, nbase, lane, acc);
            } else {
                int tb = (s >= 6) ? 2 * (s - 6) : 2 * (s - 1);
                int nt = (tb == 8) ? 1 : 2;
#pragma unroll 1
                for (int ti = 0; ti < nt; ti++) {
                    int tap = tb + ti;
                    ksteps8<18, 68, 2>(buf, ((tap / 3) * 18 + tap % 3) * 68,
                                       wc + ti * 8704, mbase, nbase, lane, acc);
                }
            }
            __syncthreads();                           // stage-s operands free
            if (s == 10) break;
            if (s == 0 || s == 5) {                    // h-halo half: 180 pix x 16 float4
                int kh = (s == 0) ? 0 : 64;
                for (int idx = t; idx < 2880; idx += 256) {
                    int pix = idx >> 4, c4 = (idx & 15) * 4;
                    int rr = pix / 18, cc = pix % 18, gr = r0 + rr - 1, gc = c0 + cc - 1;
                    bool v = gr >= 0 && gr < 128 && gc >= 0 && gc < 128;
                    cpa(s2u(buf + pix * 68 + c4),
                        hbase + ((size_t)((v ? gr : 0) * 128 + (v ? gc : 0)) * 128) + kh + c4, v);
                }
                CPC;
            }
            if (s <= 8) {                              // weights for stage s+2
                int k = s + 2;
                int kh2 = (k >= 6) ? 64 : 0;
                int tb2 = (k >= 6) ? 2 * (k - 6) : 2 * (k - 1);
                int ntap = (tb2 == 8) ? 1 : 2;
                float* wn = (s & 1) ? wb : wa;
                for (int idx = t; idx < ntap * 2048; idx += 256) {
                    int ti = idx >> 11, rem = idx & 2047;
                    int ci = rem >> 5, c4 = (rem & 31) * 4;
                    cpa(s2u(wn + ti * 8704 + ci * 136 + c4),
                        g_w2p + ((size_t)(e * 9 + tb2 + ti) * 128 + kh2 + ci) * 128 + c4, true);
                }
                CPC;
                CPW1;
            } else {
                CPW0;
            }
            __syncthreads();                           // stage s+1 operands visible
        }
        float g = gsm[e];
#pragma unroll
        for (int mt = 0; mt < 2; mt++)
#pragma unroll
            for (int nt = 0; nt < 8; nt++) {
                int co = nbase + nt * 8 + (lane & 3) * 2;
                float bb0 = bsm[e * 128 + co], bb1 = bsm[e * 128 + co + 1];
                comb[mt][nt][0] += g * fmaxf(acc[mt][nt][0] + bb0, 0.f);
                comb[mt][nt][1] += g * fmaxf(acc[mt][nt][1] + bb1, 0.f);
                comb[mt][nt][2] += g * fmaxf(acc[mt][nt][2] + bb0, 0.f);
                comb[mt][nt][3] += g * fmaxf(acc[mt][nt][3] + bb1, 0.f);
            }
    }
    float* yb = g_y + ((size_t)b << 21);
#pragma unroll
    for (int mt = 0; mt < 2; mt++) {
        int p0 = mbase + mt * 16 + (lane >> 2);
        int py = r0 + (p0 >> 4), px = c0 + (p0 & 15);
#pragma unroll
        for (int nt = 0; nt < 8; nt++) {
            int co = nbase + nt * 8 + (lane & 3) * 2;
            size_t base = ((size_t)py * 128 + px) * 128 + co;
            *(float2*)(yb + base) = make_float2(comb[mt][nt][0], comb[mt][nt][1]);
            *(float2*)(yb + base + 1024) = make_float2(comb[mt][nt][2], comb[mt][nt][3]);
        }
    }
}

// ---------------- GroupNorm partial stats (deterministic) ----------------
__global__ void gnstat_kernel() {
    __shared__ float s1[256], s2[256];
    int blk = blockIdx.x, bg = blk >> 3, part = blk & 7, b = bg >> 3, g = bg & 7;
    int t = threadIdx.x;
    const float* yb = g_y + ((size_t)b << 21);
    float s = 0.f, q = 0.f;
    for (int i = part * 32768 + t; i < part * 32768 + 32768; i += 256) {
        float v = yb[(size_t)(i >> 4) * 128 + g * 16 + (i & 15)];
        s += v; q += v * v;
    }
    s1[t] = s; s2[t] = q;
    __syncthreads();
    for (int o = 128; o; o >>= 1) {
        if (t < o) { s1[t] += s1[t + o]; s2[t] += s2[t + o]; }
        __syncthreads();
    }
    if (t == 0) { g_p1[blk] = s1[0]; g_p2[blk] = s2[0]; }
}

// ---------------- normalize + NHWC -> NCHW ----------------
__global__ void finalize_kernel(float* __restrict__ out, const float* __restrict__ gamma,
                                const float* __restrict__ beta) {
    extern __shared__ float s[];   // 128*129
    __shared__ float smu[8], sinv[8];
    int b = blockIdx.x >> 7, y = blockIdx.x & 127, t = threadIdx.x;
    if (t < 8) {
        float ss = 0.f, qq = 0.f;
        for (int p = 0; p < 8; p++) { ss += g_p1[(b * 8 + t) * 8 + p]; qq += g_p2[(b * 8 + t) * 8 + p]; }
        float mu = ss * (1.f / 262144.f);
        smu[t] = mu;
        sinv[t] = rsqrtf(qq * (1.f / 262144.f) - mu * mu + 1e-5f);
    }
    const float* yb = g_y + (((size_t)b * 16384) + y * 128) * 128;
#pragma unroll 4
    for (int i = 0; i < 64; i++) {
        int idx = i * 256 + t, xx = idx >> 7, co = idx & 127;
        s[xx * 129 + co] = yb[xx * 128 + co];
    }
    __syncthreads();
#pragma unroll 4
    for (int i = 0; i < 64; i++) {
        int idx = i * 256 + t, co = idx >> 7, xx = idx & 127, g = co >> 4;
        out[(((size_t)b * 128 + co) * 128 + y) * 128 + xx] =
            (s[xx * 129 + co] - smu[g]) * sinv[g] * gamma[co] + beta[co];
    }
}

extern "C" void kernel_launch(void* const* d_in, const int* in_sizes, int n_in,
                              void* d_out, int out_size) {
    const float* x   = (const float*)d_in[0];
    const float* W1  = (const float*)d_in[1];
    const float* b1  = (const float*)d_in[2];
    const float* W2  = (const float*)d_in[3];
    const float* b2  = (const float*)d_in[4];
    const float* Wr  = (const float*)d_in[5];
    const float* br  = (const float*)d_in[6];
    const float* Rw1 = (const float*)d_in[7];
    const float* Rb1 = (const float*)d_in[8];
    const float* Rw2 = (const float*)d_in[9];
    const float* Rb2 = (const float*)d_in[10];
    const float* gamma = (const float*)d_in[11];
    const float* beta  = (const float*)d_in[12];
    float* out = (float*)d_out;

    cudaFuncSetAttribute(conv1_kernel, cudaFuncAttributeMaxDynamicSharedMemorySize, 158272);
    cudaFuncSetAttribute(conv2_kernel, cudaFuncAttributeMaxDynamicSharedMemorySize, 192352);
    cudaFuncSetAttribute(finalize_kernel, cudaFuncAttributeMaxDynamicSharedMemorySize, 66048);

    router_kernel<<<512, 128>>>(x, Rw1, Rb1, Rw2, Rb2);
    transpose_kernel<<<1024, 256>>>(x);
    prep_kernel<<<7168, 256>>>(W1, W2, Wr);
    conv1_kernel<<<dim3(64, 8, 8), 256, 158272>>>(b1);
    conv2_kernel<<<dim3(128, 8), 256, 192352>>>(b2, br);
    gnstat_kernel<<<512, 256>>>();
    finalize_kernel<<<1024, 256, 66048>>>(out, gamma, beta);
}